// round 3
// baseline (speedup 1.0000x reference)
#include <cuda_runtime.h>
#include <math.h>

// Problem constants
#define B_  2
#define S_  2048
#define F_  1024
#define H_  16
#define D_  64
#define MTOK (B_*S_)     // 4096 tokens
#define HD   (H_*D_)     // 1024

// Device scratch (no cudaMalloc allowed)
__device__ float g_q[MTOK*HD];
__device__ float g_k[MTOK*HD];
__device__ float g_v[MTOK*HD];
__device__ float g_x[MTOK*HD];

// ---------------------------------------------------------------------------
// Generic projection GEMM: C[M=4096][N=1024] = alpha*(A[4096][1024] @ W[1024][1024] + bias)
// 64x64 tile, K-tile 16, 256 threads, 4x4 micro-tile.
// ---------------------------------------------------------------------------
__global__ __launch_bounds__(256) void gemm_proj(
    const float* __restrict__ A, const float* __restrict__ W,
    const float* __restrict__ bias, float* __restrict__ C, float alpha)
{
    __shared__ float As[16][64];
    __shared__ float Ws[16][64];
    const int tid = threadIdx.x;
    const int tx = tid % 16;        // n dir
    const int ty = tid / 16;        // m dir
    const int m0 = blockIdx.y * 64;
    const int n0 = blockIdx.x * 64;

    float acc[4][4] = {};

    for (int k0 = 0; k0 < 1024; k0 += 16) {
        // Load A tile 64x16: thread t -> row t/4, float4 seg t%4
        {
            int row = tid >> 2;
            int c4  = (tid & 3) * 4;
            float4 a4 = *reinterpret_cast<const float4*>(&A[(size_t)(m0 + row) * 1024 + k0 + c4]);
            As[c4 + 0][row] = a4.x;
            As[c4 + 1][row] = a4.y;
            As[c4 + 2][row] = a4.z;
            As[c4 + 3][row] = a4.w;
        }
        // Load W tile 16x64: thread t -> row t/16, cols (t%16)*4
        {
            int row = tid >> 4;
            int c4  = (tid & 15) * 4;
            float4 w4 = *reinterpret_cast<const float4*>(&W[(size_t)(k0 + row) * 1024 + n0 + c4]);
            *reinterpret_cast<float4*>(&Ws[row][c4]) = w4;
        }
        __syncthreads();

        #pragma unroll
        for (int kk = 0; kk < 16; kk++) {
            float4 a4 = *reinterpret_cast<const float4*>(&As[kk][ty * 4]);
            float4 b4 = *reinterpret_cast<const float4*>(&Ws[kk][tx * 4]);
            float a[4] = {a4.x, a4.y, a4.z, a4.w};
            float b[4] = {b4.x, b4.y, b4.z, b4.w};
            #pragma unroll
            for (int i = 0; i < 4; i++)
                #pragma unroll
                for (int j = 0; j < 4; j++)
                    acc[i][j] = fmaf(a[i], b[j], acc[i][j]);
        }
        __syncthreads();
    }

    #pragma unroll
    for (int i = 0; i < 4; i++) {
        int m = m0 + ty * 4 + i;
        #pragma unroll
        for (int j = 0; j < 4; j++) {
            int n = n0 + tx * 4 + j;
            C[(size_t)m * 1024 + n] = alpha * (acc[i][j] + bias[n]);
        }
    }
}

// ---------------------------------------------------------------------------
// Scores: per (b,h), logits[q][k] = sum_d Q[q][d]*K[k][d]. Only kt<=qt tiles.
// Output written into the attn region of d_out (softmax then runs in-place).
// ---------------------------------------------------------------------------
__global__ __launch_bounds__(256) void scores_kernel(float* __restrict__ attn)
{
    const int kt = blockIdx.x;
    const int qt = blockIdx.y;
    if (kt > qt) return;
    const int bh = blockIdx.z;
    const int b = bh / H_, h = bh % H_;

    const float* Qb = g_q + ((size_t)b * S_ * H_ + h) * D_;  // row stride HD
    const float* Kb = g_k + ((size_t)b * S_ * H_ + h) * D_;

    __shared__ float Qs[64][65];
    __shared__ float Ks[64][65];

    const int tid = threadIdx.x;
    const int tx = tid % 16;  // k dir
    const int ty = tid / 16;  // q dir
    const int q0 = qt * 64;
    const int k0 = kt * 64;

    // Load 64x64 tiles (row stride HD in global)
    #pragma unroll
    for (int it = 0; it < 4; it++) {
        int idx = tid + it * 256;          // 0..1023 float4 slots
        int row = idx >> 4;
        int c4  = (idx & 15) * 4;
        float4 q4 = *reinterpret_cast<const float4*>(&Qb[(size_t)(q0 + row) * HD + c4]);
        Qs[row][c4 + 0] = q4.x; Qs[row][c4 + 1] = q4.y;
        Qs[row][c4 + 2] = q4.z; Qs[row][c4 + 3] = q4.w;
        float4 k4 = *reinterpret_cast<const float4*>(&Kb[(size_t)(k0 + row) * HD + c4]);
        Ks[row][c4 + 0] = k4.x; Ks[row][c4 + 1] = k4.y;
        Ks[row][c4 + 2] = k4.z; Ks[row][c4 + 3] = k4.w;
    }
    __syncthreads();

    float acc[4][4] = {};
    #pragma unroll
    for (int d = 0; d < 64; d++) {
        float a[4], b2[4];
        #pragma unroll
        for (int i = 0; i < 4; i++) a[i] = Qs[ty * 4 + i][d];
        #pragma unroll
        for (int j = 0; j < 4; j++) b2[j] = Ks[tx * 4 + j][d];
        #pragma unroll
        for (int i = 0; i < 4; i++)
            #pragma unroll
            for (int j = 0; j < 4; j++)
                acc[i][j] = fmaf(a[i], b2[j], acc[i][j]);
    }

    #pragma unroll
    for (int i = 0; i < 4; i++) {
        int q = q0 + ty * 4 + i;
        #pragma unroll
        for (int j = 0; j < 4; j++) {
            int k = k0 + tx * 4 + j;
            attn[((size_t)bh * S_ + q) * S_ + k] = acc[i][j];
        }
    }
}

// ---------------------------------------------------------------------------
// Causal softmax in-place. One block per row (b,h,q). Row length S_, valid
// entries k <= q; masked entries written as exact 0 (matches exp(min-max)=0).
// ---------------------------------------------------------------------------
__global__ __launch_bounds__(256) void softmax_kernel(float* __restrict__ attn)
{
    const int row = blockIdx.x;            // 0 .. B*H*S-1
    const int q = row % S_;
    float* p = attn + (size_t)row * S_;
    const int len = q + 1;
    const int tid = threadIdx.x;
    const int lane = tid & 31, warp = tid >> 5;

    __shared__ float sred[8];
    __shared__ float sbc[2];

    float v[8];
    float mx = -INFINITY;
    #pragma unroll
    for (int i = 0; i < 8; i++) {
        int idx = tid + i * 256;
        v[i] = (idx < len) ? p[idx] : -INFINITY;
        mx = fmaxf(mx, v[i]);
    }
    #pragma unroll
    for (int o = 16; o > 0; o >>= 1) mx = fmaxf(mx, __shfl_xor_sync(0xffffffffu, mx, o));
    if (lane == 0) sred[warp] = mx;
    __syncthreads();
    if (tid == 0) {
        float m = sred[0];
        #pragma unroll
        for (int i = 1; i < 8; i++) m = fmaxf(m, sred[i]);
        sbc[0] = m;
    }
    __syncthreads();
    mx = sbc[0];

    float s = 0.f;
    #pragma unroll
    for (int i = 0; i < 8; i++) {
        int idx = tid + i * 256;
        float e = (idx < len) ? __expf(v[i] - mx) : 0.f;
        v[i] = e;
        s += e;
    }
    #pragma unroll
    for (int o = 16; o > 0; o >>= 1) s += __shfl_xor_sync(0xffffffffu, s, o);
    if (lane == 0) sred[warp] = s;
    __syncthreads();
    if (tid == 0) {
        float t = 0.f;
        #pragma unroll
        for (int i = 0; i < 8; i++) t += sred[i];
        sbc[1] = t;
    }
    __syncthreads();
    const float inv = 1.0f / sbc[1];

    #pragma unroll
    for (int i = 0; i < 8; i++) {
        int idx = tid + i * 256;
        p[idx] = (idx < len) ? v[i] * inv : 0.f;
    }
}

// ---------------------------------------------------------------------------
// PV: x[b][q][h][d] = sum_k attn[bh][q][k] * V[b][k][h][d]
// Per (bh, qtile): 64(q) x 64(d) output, k runs only up to (qt+1)*64 (causal).
// ---------------------------------------------------------------------------
__global__ __launch_bounds__(256) void pv_kernel(const float* __restrict__ attn)
{
    const int qt = blockIdx.x;
    const int bh = blockIdx.y;
    const int b = bh / H_, h = bh % H_;
    const float* Vb = g_v + ((size_t)b * S_ * H_ + h) * D_;
    float* Xb = g_x + ((size_t)b * S_ * H_ + h) * D_;

    __shared__ float Ps[64][65];  // [q][k]
    __shared__ float Vs[64][65];  // [k][d]

    const int tid = threadIdx.x;
    const int tx = tid % 16;   // d dir
    const int ty = tid / 16;   // q dir
    const int q0 = qt * 64;

    float acc[4][4] = {};

    for (int kt = 0; kt <= qt; kt++) {
        const int k0 = kt * 64;
        #pragma unroll
        for (int it = 0; it < 4; it++) {
            int idx = tid + it * 256;
            int row = idx >> 4;
            int c4  = (idx & 15) * 4;
            float4 p4 = *reinterpret_cast<const float4*>(
                &attn[((size_t)bh * S_ + q0 + row) * S_ + k0 + c4]);
            Ps[row][c4 + 0] = p4.x; Ps[row][c4 + 1] = p4.y;
            Ps[row][c4 + 2] = p4.z; Ps[row][c4 + 3] = p4.w;
            float4 v4 = *reinterpret_cast<const float4*>(&Vb[(size_t)(k0 + row) * HD + c4]);
            Vs[row][c4 + 0] = v4.x; Vs[row][c4 + 1] = v4.y;
            Vs[row][c4 + 2] = v4.z; Vs[row][c4 + 3] = v4.w;
        }
        __syncthreads();

        #pragma unroll 16
        for (int kk = 0; kk < 64; kk++) {
            float a[4], b2[4];
            #pragma unroll
            for (int i = 0; i < 4; i++) a[i] = Ps[ty * 4 + i][kk];
            #pragma unroll
            for (int j = 0; j < 4; j++) b2[j] = Vs[kk][tx * 4 + j];
            #pragma unroll
            for (int i = 0; i < 4; i++)
                #pragma unroll
                for (int j = 0; j < 4; j++)
                    acc[i][j] = fmaf(a[i], b2[j], acc[i][j]);
        }
        __syncthreads();
    }

    #pragma unroll
    for (int i = 0; i < 4; i++) {
        int q = q0 + ty * 4 + i;
        #pragma unroll
        for (int j = 0; j < 4; j++) {
            int d = tx * 4 + j;
            Xb[(size_t)q * HD + d] = acc[i][j];
        }
    }
}

// ---------------------------------------------------------------------------
// Launch
// ---------------------------------------------------------------------------
extern "C" void kernel_launch(void* const* d_in, const int* in_sizes, int n_in,
                              void* d_out, int out_size)
{
    const float* inputs_q  = (const float*)d_in[0];
    const float* inputs_kv = (const float*)d_in[1];
    // d_in[2] = mask (known causal, unused)
    const float* Wq = (const float*)d_in[3];
    const float* bq = (const float*)d_in[4];
    const float* Wk = (const float*)d_in[5];
    const float* bk = (const float*)d_in[6];
    const float* Wv = (const float*)d_in[7];
    const float* bv = (const float*)d_in[8];
    const float* Wo = (const float*)d_in[9];
    const float* bo = (const float*)d_in[10];

    float* out  = (float*)d_out;                       // [B,S,F]
    float* attn = out + (size_t)MTOK * F_;             // [B,H,S,S]

    float* gq; cudaGetSymbolAddress((void**)&gq, g_q);
    float* gk; cudaGetSymbolAddress((void**)&gk, g_k);
    float* gv; cudaGetSymbolAddress((void**)&gv, g_v);
    float* gx; cudaGetSymbolAddress((void**)&gx, g_x);

    dim3 gproj(F_ / 64, MTOK / 64);   // (16, 64)
    const float qscale = 0.125f;      // 1/sqrt(Dh)

    gemm_proj<<<gproj, 256>>>(inputs_q,  Wq, bq, gq, qscale);
    gemm_proj<<<gproj, 256>>>(inputs_kv, Wk, bk, gk, 1.0f);
    gemm_proj<<<gproj, 256>>>(inputs_kv, Wv, bv, gv, 1.0f);

    dim3 gsc(S_ / 64, S_ / 64, B_ * H_);  // (32, 32, 32)
    scores_kernel<<<gsc, 256>>>(attn);

    softmax_kernel<<<B_ * H_ * S_, 256>>>(attn);

    dim3 gpv(S_ / 64, B_ * H_);           // (32, 32)
    pv_kernel<<<gpv, 256>>>(attn);

    gemm_proj<<<gproj, 256>>>(gx, Wo, bo, out, 1.0f);
}

// round 6
// speedup vs baseline: 1.3046x; 1.3046x over previous
#include <cuda_runtime.h>
#include <math.h>

// Problem constants
#define B_  2
#define S_  2048
#define F_  1024
#define H_  16
#define D_  64
#define MTOK (B_*S_)     // 4096 tokens
#define HD   (H_*D_)     // 1024

// Device scratch (no cudaMalloc allowed)
__device__ float g_q[MTOK*HD];
__device__ float g_k[MTOK*HD];
__device__ float g_v[MTOK*HD];
__device__ float g_x[MTOK*HD];

// ---------------------------------------------------------------------------
// Projection GEMM: C[4096][1024] = alpha*(A[4096][1024] @ W[1024][1024] + bias)
// 128x128 tile, K-chunk 32, 256 threads, 8x8 micro-tile (split halves).
// ---------------------------------------------------------------------------
__global__ __launch_bounds__(256, 2) void gemm_proj(
    const float* __restrict__ A, const float* __restrict__ W,
    const float* __restrict__ bias, float* __restrict__ C, float alpha)
{
    __shared__ float At[32][132];   // [k][m] transposed
    __shared__ float Ws[32][132];   // [k][n]
    const int tid = threadIdx.x;
    const int tx = tid & 15;        // n dir
    const int ty = tid >> 4;        // m dir
    const int m0 = blockIdx.y * 128;
    const int n0 = blockIdx.x * 128;

    float acc[8][8] = {};

    for (int k0 = 0; k0 < 1024; k0 += 32) {
        // A tile: 128 rows(m) x 32 cols(k), transposed into At[k][m]
        #pragma unroll
        for (int it = 0; it < 4; it++) {
            int idx = tid + it * 256;           // 0..1023
            int row = idx >> 3;                 // 0..127
            int c4  = (idx & 7) * 4;            // 0..28
            float4 a4 = *reinterpret_cast<const float4*>(&A[(size_t)(m0 + row) * 1024 + k0 + c4]);
            At[c4 + 0][row] = a4.x; At[c4 + 1][row] = a4.y;
            At[c4 + 2][row] = a4.z; At[c4 + 3][row] = a4.w;
        }
        // W tile: 32 rows(k) x 128 cols(n), natural layout
        #pragma unroll
        for (int it = 0; it < 4; it++) {
            int idx = tid + it * 256;           // 0..1023
            int row = idx >> 5;                 // 0..31
            int c4  = (idx & 31) * 4;           // 0..124
            *reinterpret_cast<float4*>(&Ws[row][c4]) =
                *reinterpret_cast<const float4*>(&W[(size_t)(k0 + row) * 1024 + n0 + c4]);
        }
        __syncthreads();

        #pragma unroll 4
        for (int kk = 0; kk < 32; kk++) {
            float a[8], b[8];
            *reinterpret_cast<float4*>(&a[0]) = *reinterpret_cast<const float4*>(&At[kk][ty * 4]);
            *reinterpret_cast<float4*>(&a[4]) = *reinterpret_cast<const float4*>(&At[kk][64 + ty * 4]);
            *reinterpret_cast<float4*>(&b[0]) = *reinterpret_cast<const float4*>(&Ws[kk][tx * 4]);
            *reinterpret_cast<float4*>(&b[4]) = *reinterpret_cast<const float4*>(&Ws[kk][64 + tx * 4]);
            #pragma unroll
            for (int i = 0; i < 8; i++)
                #pragma unroll
                for (int j = 0; j < 8; j++)
                    acc[i][j] = fmaf(a[i], b[j], acc[i][j]);
        }
        __syncthreads();
    }

    #pragma unroll
    for (int i = 0; i < 8; i++) {
        int m = m0 + ((i < 4) ? (ty * 4 + i) : (64 + ty * 4 + i - 4));
        float* crow = &C[(size_t)m * 1024 + n0];
        #pragma unroll
        for (int half = 0; half < 2; half++) {
            int n = half * 64 + tx * 4;
            float4 r;
            r.x = alpha * (acc[i][half * 4 + 0] + bias[n0 + n + 0]);
            r.y = alpha * (acc[i][half * 4 + 1] + bias[n0 + n + 1]);
            r.z = alpha * (acc[i][half * 4 + 2] + bias[n0 + n + 2]);
            r.w = alpha * (acc[i][half * 4 + 3] + bias[n0 + n + 3]);
            *reinterpret_cast<float4*>(&crow[n]) = r;
        }
    }
}

// ---------------------------------------------------------------------------
// Scores: logits[q][k] = sum_d Q[q][d]*K[k][d], 128x128 tile, causal tiles only.
// ---------------------------------------------------------------------------
__global__ __launch_bounds__(256, 2) void scores_kernel(float* __restrict__ attn)
{
    const int kt = blockIdx.x;
    const int qt = blockIdx.y;
    if (kt > qt) return;
    const int bh = blockIdx.z;
    const int b = bh >> 4, h = bh & 15;

    const float* Qb = g_q + ((size_t)b * S_ * H_ + h) * D_;
    const float* Kb = g_k + ((size_t)b * S_ * H_ + h) * D_;

    __shared__ float Qt[32][132];   // [d][q]
    __shared__ float Kt[32][132];   // [d][k]

    const int tid = threadIdx.x;
    const int tx = tid & 15;   // k dir
    const int ty = tid >> 4;   // q dir
    const int q0 = qt * 128;
    const int k0 = kt * 128;

    float acc[8][8] = {};

    for (int c = 0; c < 64; c += 32) {
        #pragma unroll
        for (int it = 0; it < 4; it++) {
            int idx = tid + it * 256;
            int row = idx >> 3;          // 0..127
            int c4  = (idx & 7) * 4;     // 0..28
            float4 q4 = *reinterpret_cast<const float4*>(&Qb[(size_t)(q0 + row) * HD + c + c4]);
            Qt[c4 + 0][row] = q4.x; Qt[c4 + 1][row] = q4.y;
            Qt[c4 + 2][row] = q4.z; Qt[c4 + 3][row] = q4.w;
            float4 k4 = *reinterpret_cast<const float4*>(&Kb[(size_t)(k0 + row) * HD + c + c4]);
            Kt[c4 + 0][row] = k4.x; Kt[c4 + 1][row] = k4.y;
            Kt[c4 + 2][row] = k4.z; Kt[c4 + 3][row] = k4.w;
        }
        __syncthreads();

        #pragma unroll 4
        for (int d = 0; d < 32; d++) {
            float a[8], b2[8];
            *reinterpret_cast<float4*>(&a[0]) = *reinterpret_cast<const float4*>(&Qt[d][ty * 4]);
            *reinterpret_cast<float4*>(&a[4]) = *reinterpret_cast<const float4*>(&Qt[d][64 + ty * 4]);
            *reinterpret_cast<float4*>(&b2[0]) = *reinterpret_cast<const float4*>(&Kt[d][tx * 4]);
            *reinterpret_cast<float4*>(&b2[4]) = *reinterpret_cast<const float4*>(&Kt[d][64 + tx * 4]);
            #pragma unroll
            for (int i = 0; i < 8; i++)
                #pragma unroll
                for (int j = 0; j < 8; j++)
                    acc[i][j] = fmaf(a[i], b2[j], acc[i][j]);
        }
        __syncthreads();
    }

    #pragma unroll
    for (int i = 0; i < 8; i++) {
        int q = q0 + ((i < 4) ? (ty * 4 + i) : (64 + ty * 4 + i - 4));
        float* dst = &attn[((size_t)bh * S_ + q) * S_ + k0];
        *reinterpret_cast<float4*>(&dst[tx * 4]) =
            make_float4(acc[i][0], acc[i][1], acc[i][2], acc[i][3]);
        *reinterpret_cast<float4*>(&dst[64 + tx * 4]) =
            make_float4(acc[i][4], acc[i][5], acc[i][6], acc[i][7]);
    }
}

// ---------------------------------------------------------------------------
// Causal softmax in-place. One block per row (b,h,q); masked entries -> 0.
// ---------------------------------------------------------------------------
__global__ __launch_bounds__(256) void softmax_kernel(float* __restrict__ attn)
{
    const int row = blockIdx.x;            // 0 .. B*H*S-1
    const int q = row % S_;
    float* p = attn + (size_t)row * S_;
    const int len = q + 1;
    const int tid = threadIdx.x;
    const int lane = tid & 31, warp = tid >> 5;

    __shared__ float sred[8];
    __shared__ float sbc[2];

    float v[8];
    float mx = -INFINITY;
    #pragma unroll
    for (int i = 0; i < 8; i++) {
        int idx = tid + i * 256;
        v[i] = (idx < len) ? p[idx] : -INFINITY;
        mx = fmaxf(mx, v[i]);
    }
    #pragma unroll
    for (int o = 16; o > 0; o >>= 1) mx = fmaxf(mx, __shfl_xor_sync(0xffffffffu, mx, o));
    if (lane == 0) sred[warp] = mx;
    __syncthreads();
    if (tid == 0) {
        float m = sred[0];
        #pragma unroll
        for (int i = 1; i < 8; i++) m = fmaxf(m, sred[i]);
        sbc[0] = m;
    }
    __syncthreads();
    mx = sbc[0];

    float s = 0.f;
    #pragma unroll
    for (int i = 0; i < 8; i++) {
        int idx = tid + i * 256;
        float e = (idx < len) ? __expf(v[i] - mx) : 0.f;
        v[i] = e;
        s += e;
    }
    #pragma unroll
    for (int o = 16; o > 0; o >>= 1) s += __shfl_xor_sync(0xffffffffu, s, o);
    if (lane == 0) sred[warp] = s;
    __syncthreads();
    if (tid == 0) {
        float t = 0.f;
        #pragma unroll
        for (int i = 0; i < 8; i++) t += sred[i];
        sbc[1] = t;
    }
    __syncthreads();
    const float inv = 1.0f / sbc[1];

    #pragma unroll
    for (int i = 0; i < 8; i++) {
        int idx = tid + i * 256;
        p[idx] = (idx < len) ? v[i] * inv : 0.f;
    }
}

// ---------------------------------------------------------------------------
// PV: x[q][d] = sum_k attn[q][k] * V[k][d].  128(q) x 64(d) tiles, 8x4 micro.
// Triangle pairing: block pair i handles q-tiles i and 15-i -> uniform work,
// one balanced wave of 256 blocks.
// ---------------------------------------------------------------------------
__device__ __forceinline__ void pv_tile(
    const float* __restrict__ attn, const float* __restrict__ Vb,
    float* __restrict__ Xb, int bh, int qt, int tid)
{
    __shared__ float Pt[32][132];   // [k][q]
    __shared__ float Vs[32][68];    // [k][d]

    const int tx = tid & 15;   // d dir (16 * 4 = 64)
    const int ty = tid >> 4;   // q dir (16 * 8 = 128)
    const int q0 = qt * 128;
    const int kend = (qt + 1) * 128;   // softmax zeroed k>q, safe to include

    float acc[8][4] = {};

    for (int k0 = 0; k0 < kend; k0 += 32) {
        // P tile: 128 rows(q) x 32 cols(k), transposed
        #pragma unroll
        for (int it = 0; it < 4; it++) {
            int idx = tid + it * 256;
            int row = idx >> 3;          // 0..127
            int c4  = (idx & 7) * 4;
            float4 p4 = *reinterpret_cast<const float4*>(
                &attn[((size_t)bh * S_ + q0 + row) * S_ + k0 + c4]);
            Pt[c4 + 0][row] = p4.x; Pt[c4 + 1][row] = p4.y;
            Pt[c4 + 2][row] = p4.z; Pt[c4 + 3][row] = p4.w;
        }
        // V tile: 32 rows(k) x 64 cols(d)
        #pragma unroll
        for (int it = 0; it < 2; it++) {
            int idx = tid + it * 256;    // 0..511
            int row = idx >> 4;          // 0..31
            int c4  = (idx & 15) * 4;    // 0..60
            *reinterpret_cast<float4*>(&Vs[row][c4]) =
                *reinterpret_cast<const float4*>(&Vb[(size_t)(k0 + row) * HD + c4]);
        }
        __syncthreads();

        #pragma unroll 4
        for (int kk = 0; kk < 32; kk++) {
            float a[8], b2[4];
            *reinterpret_cast<float4*>(&a[0]) = *reinterpret_cast<const float4*>(&Pt[kk][ty * 4]);
            *reinterpret_cast<float4*>(&a[4]) = *reinterpret_cast<const float4*>(&Pt[kk][64 + ty * 4]);
            *reinterpret_cast<float4*>(&b2[0]) = *reinterpret_cast<const float4*>(&Vs[kk][tx * 4]);
            #pragma unroll
            for (int i = 0; i < 8; i++)
                #pragma unroll
                for (int j = 0; j < 4; j++)
                    acc[i][j] = fmaf(a[i], b2[j], acc[i][j]);
        }
        __syncthreads();
    }

    #pragma unroll
    for (int i = 0; i < 8; i++) {
        int q = q0 + ((i < 4) ? (ty * 4 + i) : (64 + ty * 4 + i - 4));
        *reinterpret_cast<float4*>(&Xb[(size_t)q * HD + tx * 4]) =
            make_float4(acc[i][0], acc[i][1], acc[i][2], acc[i][3]);
    }
}

__global__ __launch_bounds__(256, 2) void pv_kernel(const float* __restrict__ attn)
{
    const int pair = blockIdx.x;           // 0..7
    const int bh = blockIdx.y;
    const int b = bh >> 4, h = bh & 15;
    const float* Vb = g_v + ((size_t)b * S_ * H_ + h) * D_;
    float* Xb = g_x + ((size_t)b * S_ * H_ + h) * D_;
    const int tid = threadIdx.x;

    pv_tile(attn, Vb, Xb, bh, pair, tid);          // light tile
    pv_tile(attn, Vb, Xb, bh, 15 - pair, tid);     // heavy tile
}

// ---------------------------------------------------------------------------
// Launch
// ---------------------------------------------------------------------------
extern "C" void kernel_launch(void* const* d_in, const int* in_sizes, int n_in,
                              void* d_out, int out_size)
{
    const float* inputs_q  = (const float*)d_in[0];
    const float* inputs_kv = (const float*)d_in[1];
    // d_in[2] = mask (known causal, unused)
    const float* Wq = (const float*)d_in[3];
    const float* bq = (const float*)d_in[4];
    const float* Wk = (const float*)d_in[5];
    const float* bk = (const float*)d_in[6];
    const float* Wv = (const float*)d_in[7];
    const float* bv = (const float*)d_in[8];
    const float* Wo = (const float*)d_in[9];
    const float* bo = (const float*)d_in[10];

    float* out  = (float*)d_out;                       // [B,S,F]
    float* attn = out + (size_t)MTOK * F_;             // [B,H,S,S]

    float* gq; cudaGetSymbolAddress((void**)&gq, g_q);
    float* gk; cudaGetSymbolAddress((void**)&gk, g_k);
    float* gv; cudaGetSymbolAddress((void**)&gv, g_v);
    float* gx; cudaGetSymbolAddress((void**)&gx, g_x);

    dim3 gproj(F_ / 128, MTOK / 128);   // (8, 32)
    const float qscale = 0.125f;        // 1/sqrt(Dh)

    gemm_proj<<<gproj, 256>>>(inputs_q,  Wq, bq, gq, qscale);
    gemm_proj<<<gproj, 256>>>(inputs_kv, Wk, bk, gk, 1.0f);
    gemm_proj<<<gproj, 256>>>(inputs_kv, Wv, bv, gv, 1.0f);

    dim3 gsc(S_ / 128, S_ / 128, B_ * H_);  // (16, 16, 32)
    scores_kernel<<<gsc, 256>>>(attn);

    softmax_kernel<<<B_ * H_ * S_, 256>>>(attn);

    dim3 gpv(S_ / 256, B_ * H_);            // (8, 32) triangle pairs
    pv_kernel<<<gpv, 256>>>(attn);

    gemm_proj<<<gproj, 256>>>(gx, Wo, bo, out, 1.0f);
}